// round 17
// baseline (speedup 1.0000x reference)
#include <cuda_runtime.h>
#include <cuda_bf16.h>
#include <math.h>

#define Bsz 8
#define Dd 512
#define Hh 8
#define Ee 64
#define DI 1024
#define Ss 64
#define Rr 32
#define DFF 2048
#define LL 1152
#define Mrows (Bsz*LL)   /* 9216 */
#define QKVN 1536

// ---------------- scratch (static __device__, no allocation) ----------------
__device__ __nv_bfloat16 g_xbf[Mrows*Dd];
__device__ __nv_bfloat16 g_wqkv[QKVN*Dd];
__device__ float         g_bqkv[QKVN];
__device__ __nv_bfloat16 g_wo[Dd*Dd];
__device__ __nv_bfloat16 g_win[2*DI*Dd];
__device__ __nv_bfloat16 g_wout[Dd*DI];
__device__ __nv_bfloat16 g_wf1[DFF*Dd];
__device__ __nv_bfloat16 g_wf2[Dd*DFF];
__device__ __nv_bfloat16 g_qkv[Mrows*QKVN];
__device__ __nv_bfloat16 g_attnO[Mrows*Dd];
__device__ float g_attn_out[Mrows*Dd];
__device__ float g_xz[Mrows*2*DI];
__device__ float g_uact[Mrows*DI];
__device__ float g_xdbc[Mrows*160];
__device__ __nv_bfloat16 g_y[Mrows*DI];
__device__ float g_hsum[Mrows*Dd];
__device__ float g_h[Mrows*Dd];
__device__ __nv_bfloat16 g_hn[Mrows*Dd];
__device__ __nv_bfloat16 g_mid[Mrows*DFF];

enum { EPI_NONE = 0, EPI_SOFTPLUS = 1, EPI_GELU = 2, EPI_ADD = 3, EPI_ADD2 = 4 };

__device__ __forceinline__ unsigned f2tf32(float f)
{
    unsigned u;
    asm("cvt.rna.tf32.f32 %0, %1;" : "=r"(u) : "f"(f));
    return u;
}

__device__ __forceinline__ void mma_tf32(float* c, const unsigned* a, const unsigned* b)
{
    asm volatile(
        "mma.sync.aligned.m16n8k8.row.col.f32.tf32.tf32.f32 "
        "{%0,%1,%2,%3},{%4,%5,%6,%7},{%8,%9},{%0,%1,%2,%3};"
        : "+f"(c[0]), "+f"(c[1]), "+f"(c[2]), "+f"(c[3])
        : "r"(a[0]), "r"(a[1]), "r"(a[2]), "r"(a[3]), "r"(b[0]), "r"(b[1]));
}

__device__ __forceinline__ void mma_bf16(float* c, const unsigned* a, const unsigned* b)
{
    asm volatile(
        "mma.sync.aligned.m16n8k16.row.col.f32.bf16.bf16.f32 "
        "{%0,%1,%2,%3},{%4,%5,%6,%7},{%8,%9},{%0,%1,%2,%3};"
        : "+f"(c[0]), "+f"(c[1]), "+f"(c[2]), "+f"(c[3])
        : "r"(a[0]), "r"(a[1]), "r"(a[2]), "r"(a[3]), "r"(b[0]), "r"(b[1]));
}

__device__ __forceinline__ void ldsm4(unsigned* r, unsigned saddr)
{
    asm volatile("ldmatrix.sync.aligned.m8n8.x4.shared.b16 {%0,%1,%2,%3}, [%4];"
        : "=r"(r[0]), "=r"(r[1]), "=r"(r[2]), "=r"(r[3]) : "r"(saddr));
}

__device__ __forceinline__ void ldsm4t(unsigned* r, unsigned saddr)
{
    asm volatile("ldmatrix.sync.aligned.m8n8.x4.trans.shared.b16 {%0,%1,%2,%3}, [%4];"
        : "=r"(r[0]), "=r"(r[1]), "=r"(r[2]), "=r"(r[3]) : "r"(saddr));
}

__device__ __forceinline__ void cpa16(unsigned d, const void* s)
{
    asm volatile("cp.async.cg.shared.global [%0], [%1], 16;" :: "r"(d), "l"(s));
}
__device__ __forceinline__ void cpa_commit()
{
    asm volatile("cp.async.commit_group;");
}
template<int NN> __device__ __forceinline__ void cpa_wait()
{
    asm volatile("cp.async.wait_group %0;" :: "n"(NN));
}

__device__ __forceinline__ uint2 pack4(float4 f)
{
    __nv_bfloat162 p0 = __floats2bfloat162_rn(f.x, f.y);
    __nv_bfloat162 p1 = __floats2bfloat162_rn(f.z, f.w);
    uint2 u;
    u.x = *(unsigned*)&p0;
    u.y = *(unsigned*)&p1;
    return u;
}

__device__ __forceinline__ unsigned packbf2(float a, float b)
{
    __nv_bfloat162 p = __floats2bfloat162_rn(a, b);
    return *(unsigned*)&p;
}

__device__ __forceinline__ float epi_apply_scalar(int EPI, float v)
{
    if (EPI == EPI_SOFTPLUS) return (v > 20.f) ? v : log1pf(expf(v));
    if (EPI == EPI_GELU)     return 0.5f*v*(1.f + erff(v*0.7071067811865475f));
    return v;
}

// ---------------- fp32 -> bf16 conversion (rn, identical to staging cvt) -----
__global__ void cvt_bf_k(const float* __restrict__ s, __nv_bfloat16* __restrict__ d, int n)
{
    int i = (blockIdx.x * 256 + threadIdx.x) * 4;
    if (i < n) {
        float4 v = *(const float4*)(s + i);
        *(uint2*)(d + i) = pack4(v);
    }
}

__global__ void concat_bias_k(const float* __restrict__ a, const float* __restrict__ b,
                              const float* __restrict__ c, float* __restrict__ d)
{
    int i = blockIdx.x * 256 + threadIdx.x;
    if (i < QKVN)
        d[i] = (i < Dd) ? a[i] : (i < 2*Dd) ? b[i - Dd] : c[i - 2*Dd];
}

// ====== all-bf16 GEMM with cp.async staging: C = A(MxK) @ W(NxK)^T ===========
template<int EPI, int OBF>
__global__ __launch_bounds__(256, 2) void gemm_bb(
    const __nv_bfloat16* __restrict__ A, int lda,
    const __nv_bfloat16* __restrict__ W,
    const float* __restrict__ bias,
    const float* __restrict__ add,
    const float* __restrict__ add2,
    void* __restrict__ Cv, int M, int N, int K)
{
    __shared__ __align__(16) char sm[2*16384 + 2*8192];
    char* AsP = sm;
    char* BsP = sm + 2*16384;
    const unsigned asU = (unsigned)__cvta_generic_to_shared(AsP);
    const unsigned bsU = (unsigned)__cvta_generic_to_shared(BsP);

    const int tid = threadIdx.x;
    const int lane = tid & 31, w = tid >> 5;
    const int warpM = w & 3, warpN = w >> 2;
    const int m0 = blockIdx.y * 128, n0 = blockIdx.x * 64;

    const int arow = tid >> 1, ag0 = (tid & 1) * 4;
    const __nv_bfloat16* Ap = A + (size_t)(m0 + arow) * lda + ag0*8;
    unsigned adst[4];
#pragma unroll
    for (int i = 0; i < 4; i++)
        adst[i] = asU + arow*128 + (((ag0 + i) ^ (arow & 7)) << 4);

    const int brow = tid >> 2, bg0 = (tid & 3) * 2;
    const __nv_bfloat16* Bp = W + (size_t)(n0 + brow) * K + bg0*8;
    unsigned bdst[2];
#pragma unroll
    for (int i = 0; i < 2; i++)
        bdst[i] = bsU + brow*128 + (((bg0 + i) ^ (brow & 7)) << 4);

    const int lr = (lane & 7) + ((lane >> 3) & 1) * 8;
    const int ko = (lane >> 4);
    int rA[2], mA[2];
#pragma unroll
    for (int mi = 0; mi < 2; mi++) {
        int r = warpM*32 + mi*16 + lr;
        rA[mi] = r * 128; mA[mi] = r & 7;
    }
    int rB[2], mB[2];
#pragma unroll
    for (int nh = 0; nh < 2; nh++) {
        int r = warpN*32 + nh*16 + lr;
        rB[nh] = r * 128; mB[nh] = r & 7;
    }

    float acc[2][4][4];
#pragma unroll
    for (int mi = 0; mi < 2; mi++)
#pragma unroll
        for (int nf = 0; nf < 4; nf++)
#pragma unroll
            for (int j = 0; j < 4; j++) acc[mi][nf][j] = 0.f;

    const int nk = K >> 6;

#pragma unroll
    for (int i = 0; i < 4; i++) cpa16(adst[i], Ap + i*8);
#pragma unroll
    for (int i = 0; i < 2; i++) cpa16(bdst[i], Bp + i*8);
    cpa_commit();

    for (int kt = 0; kt < nk; kt++) {
        const int cur = kt & 1;
        const bool more = (kt + 1) < nk;
        if (more) {
            const int nxt = cur ^ 1;
            const int kof = (kt + 1) << 6;
#pragma unroll
            for (int i = 0; i < 4; i++) cpa16(adst[i] + nxt*16384, Ap + kof + i*8);
#pragma unroll
            for (int i = 0; i < 2; i++) cpa16(bdst[i] + nxt*8192,  Bp + kof + i*8);
            cpa_commit();
            cpa_wait<1>();
        } else {
            cpa_wait<0>();
        }
        __syncthreads();

        const unsigned aB = asU + cur*16384;
        const unsigned bB = bsU + cur*8192;
#pragma unroll
        for (int ks = 0; ks < 4; ks++) {
            const int kx = 2*ks + ko;
            unsigned afr[2][4], bfr[2][4];
#pragma unroll
            for (int mi = 0; mi < 2; mi++)
                ldsm4(afr[mi], aB + rA[mi] + ((kx ^ mA[mi]) << 4));
#pragma unroll
            for (int nh = 0; nh < 2; nh++)
                ldsm4(bfr[nh], bB + rB[nh] + ((kx ^ mB[nh]) << 4));
#pragma unroll
            for (int mi = 0; mi < 2; mi++) {
                unsigned b0[2] = {bfr[0][0], bfr[0][2]};
                unsigned b1[2] = {bfr[0][1], bfr[0][3]};
                unsigned b2[2] = {bfr[1][0], bfr[1][2]};
                unsigned b3[2] = {bfr[1][1], bfr[1][3]};
                mma_bf16(acc[mi][0], afr[mi], b0);
                mma_bf16(acc[mi][1], afr[mi], b1);
                mma_bf16(acc[mi][2], afr[mi], b2);
                mma_bf16(acc[mi][3], afr[mi], b3);
            }
        }
        __syncthreads();
    }

#pragma unroll
    for (int mi = 0; mi < 2; mi++) {
#pragma unroll
        for (int nf = 0; nf < 4; nf++) {
            int row = m0 + warpM*32 + mi*16 + (lane >> 2);
            int col = n0 + warpN*32 + nf*8 + (lane & 3)*2;
            float v00 = acc[mi][nf][0], v01 = acc[mi][nf][1];
            float v10 = acc[mi][nf][2], v11 = acc[mi][nf][3];
            if (bias) {
                float b0 = bias[col], b1 = bias[col+1];
                v00 += b0; v01 += b1; v10 += b0; v11 += b1;
            }
            if (EPI == EPI_ADD || EPI == EPI_ADD2) {
                const float* ap0 = add + (size_t)row * N + col;
                const float* ap1 = add + (size_t)(row+8) * N + col;
                v00 += ap0[0]; v01 += ap0[1]; v10 += ap1[0]; v11 += ap1[1];
                if (EPI == EPI_ADD2) {
                    const float* bp0 = add2 + (size_t)row * N + col;
                    const float* bp1 = add2 + (size_t)(row+8) * N + col;
                    v00 += bp0[0]; v01 += bp0[1]; v10 += bp1[0]; v11 += bp1[1];
                }
            } else {
                v00 = epi_apply_scalar(EPI, v00); v01 = epi_apply_scalar(EPI, v01);
                v10 = epi_apply_scalar(EPI, v10); v11 = epi_apply_scalar(EPI, v11);
            }
            if (OBF) {
                __nv_bfloat16* C16 = (__nv_bfloat16*)Cv;
                *(unsigned*)&C16[(size_t)row * N + col]     = packbf2(v00, v01);
                *(unsigned*)&C16[(size_t)(row+8) * N + col] = packbf2(v10, v11);
            } else {
                float* C = (float*)Cv;
                *(float2*)&C[(size_t)row * N + col]     = make_float2(v00, v01);
                *(float2*)&C[(size_t)(row+8) * N + col] = make_float2(v10, v11);
            }
        }
    }
}

// ================= tf32 tensor-core GEMM (x_proj: B/C scan inputs) ===========
template<int EPI>
__global__ __launch_bounds__(256) void gemm_tf32(
    const float* __restrict__ A, int lda,
    const float* __restrict__ W,
    const float* __restrict__ bias,
    float* __restrict__ C, int M, int N, int K)
{
    __shared__ __align__(16) unsigned As[2][128*32];
    __shared__ __align__(16) unsigned Bs[2][64*32];

    const int t = threadIdx.x;
    const int m0 = blockIdx.y * 128, n0 = blockIdx.x * 64;
    const int lane = t & 31, w = t >> 5;
    const int warpM = w & 3, warpN = w >> 2;
    const int s = lane >> 2, off = lane & 3;

    const float* aptr[4]; int aso[4];
#pragma unroll
    for (int i = 0; i < 4; i++) {
        int e = t + i*256;
        int m = e >> 3, g = e & 7;
        aptr[i] = A + (size_t)(m0 + m) * lda + g*4;
        aso[i]  = m*32 + ((g ^ (m & 7)) << 2);
    }
    const float* bptr[2]; int bso[2]; bool bval[2];
#pragma unroll
    for (int i = 0; i < 2; i++) {
        int e = t + i*256;
        int n = e >> 3, g = e & 7;
        bval[i] = (n0 + n) < N;
        bptr[i] = W + (size_t)(n0 + n) * K + g*4;
        bso[i]  = n*32 + ((g ^ (n & 7)) << 2);
    }

    float acc[2][4][4];
#pragma unroll
    for (int mi = 0; mi < 2; mi++)
#pragma unroll
        for (int ni = 0; ni < 4; ni++)
#pragma unroll
            for (int j = 0; j < 4; j++) acc[mi][ni][j] = 0.f;

    const int nk = K >> 5;
    float4 ar[4], br[2];

#pragma unroll
    for (int i = 0; i < 4; i++) ar[i] = *(const float4*)(aptr[i]);
#pragma unroll
    for (int i = 0; i < 2; i++)
        br[i] = bval[i] ? *(const float4*)(bptr[i]) : make_float4(0.f,0.f,0.f,0.f);
#pragma unroll
    for (int i = 0; i < 4; i++)
        *(uint4*)&As[0][aso[i]] = make_uint4(f2tf32(ar[i].x), f2tf32(ar[i].y), f2tf32(ar[i].z), f2tf32(ar[i].w));
#pragma unroll
    for (int i = 0; i < 2; i++)
        *(uint4*)&Bs[0][bso[i]] = make_uint4(f2tf32(br[i].x), f2tf32(br[i].y), f2tf32(br[i].z), f2tf32(br[i].w));
    __syncthreads();

    for (int kt = 0; kt < nk; kt++) {
        const int cur = kt & 1, nxt = cur ^ 1;
        const bool more = (kt + 1) < nk;
        if (more) {
            const int ko = (kt + 1) * 32;
#pragma unroll
            for (int i = 0; i < 4; i++) ar[i] = *(const float4*)(aptr[i] + ko);
#pragma unroll
            for (int i = 0; i < 2; i++)
                br[i] = bval[i] ? *(const float4*)(bptr[i] + ko) : make_float4(0.f,0.f,0.f,0.f);
        }

#pragma unroll
        for (int ks = 0; ks < 4; ks++) {
            const int x0 = (((ks*2)     ^ s) << 2) + off;
            const int x1 = (((ks*2 + 1) ^ s) << 2) + off;
            unsigned a[2][4];
#pragma unroll
            for (int mi = 0; mi < 2; mi++) {
                int r = (warpM*32 + mi*16 + s) * 32;
                a[mi][0] = As[cur][r + x0];
                a[mi][1] = As[cur][r + 256 + x0];
                a[mi][2] = As[cur][r + x1];
                a[mi][3] = As[cur][r + 256 + x1];
            }
            unsigned b[4][2];
#pragma unroll
            for (int ni = 0; ni < 4; ni++) {
                int rb = (warpN*32 + ni*8 + s) * 32;
                b[ni][0] = Bs[cur][rb + x0];
                b[ni][1] = Bs[cur][rb + x1];
            }
#pragma unroll
            for (int mi = 0; mi < 2; mi++)
#pragma unroll
                for (int ni = 0; ni < 4; ni++)
                    mma_tf32(acc[mi][ni], a[mi], b[ni]);
        }

        if (more) {
#pragma unroll
            for (int i = 0; i < 4; i++)
                *(uint4*)&As[nxt][aso[i]] = make_uint4(f2tf32(ar[i].x), f2tf32(ar[i].y), f2tf32(ar[i].z), f2tf32(ar[i].w));
#pragma unroll
            for (int i = 0; i < 2; i++)
                *(uint4*)&Bs[nxt][bso[i]] = make_uint4(f2tf32(br[i].x), f2tf32(br[i].y), f2tf32(br[i].z), f2tf32(br[i].w));
            __syncthreads();
        }
    }

#pragma unroll
    for (int mi = 0; mi < 2; mi++) {
#pragma unroll
        for (int ni = 0; ni < 4; ni++) {
            int row = m0 + warpM*32 + mi*16 + s;
            int col = n0 + warpN*32 + ni*8 + off*2;
            if (col < N) {
                float v00 = acc[mi][ni][0], v01 = acc[mi][ni][1];
                float v10 = acc[mi][ni][2], v11 = acc[mi][ni][3];
                if (bias) {
                    float b0 = bias[col], b1 = bias[col+1];
                    v00 += b0; v01 += b1; v10 += b0; v11 += b1;
                }
                v00 = epi_apply_scalar(EPI, v00); v01 = epi_apply_scalar(EPI, v01);
                v10 = epi_apply_scalar(EPI, v10); v11 = epi_apply_scalar(EPI, v11);
                *(float2*)&C[(size_t)row * N + col]     = make_float2(v00, v01);
                *(float2*)&C[(size_t)(row+8) * N + col] = make_float2(v10, v11);
            }
        }
    }
}

// ============== bf16 tensor-core flash attention (fused QKV input) ===========
__global__ __launch_bounds__(256, 2) void attn_bf(
    const __nv_bfloat16* __restrict__ qkv, const unsigned char* __restrict__ mask,
    __nv_bfloat16* __restrict__ o)
{
    extern __shared__ __align__(16) char smA[];
    char* sQ = smA;
    char* sK = smA + 16384;
    char* sV = smA + 24576;
    const int tid = threadIdx.x;
    const int lane = tid & 31, w = tid >> 5;
    char* sP = smA + 32768 + w*2048;
    const unsigned uQ = (unsigned)__cvta_generic_to_shared(sQ);
    const unsigned uK = (unsigned)__cvta_generic_to_shared(sK);
    const unsigned uV = (unsigned)__cvta_generic_to_shared(sV);
    const unsigned uP = (unsigned)__cvta_generic_to_shared(sP);

    const int qt = blockIdx.x, h = blockIdx.y, b = blockIdx.z;
    const size_t bL = (size_t)b * LL;
    const int qr = qt * 128;

    const int lr = (lane & 7) + ((lane >> 3) & 1) * 8;
    const int ko = lane >> 4;
    const int s = lane >> 2, off = lane & 3;

    const __nv_bfloat16* qp = qkv + h*Ee;
    const __nv_bfloat16* kp = qkv + Dd + h*Ee;
    const __nv_bfloat16* vp = qkv + 2*Dd + h*Ee;

#pragma unroll
    for (int i = 0; i < 4; i++) {
        int u = tid + i*256;
        int row = u >> 3, g = u & 7;
        uint4 val = *(const uint4*)&qp[(bL + qr + row) * QKVN + g*8];
        *(uint4*)(sQ + row*128 + ((g ^ (row & 7)) << 4)) = val;
    }
    __syncthreads();

    unsigned qa[4][4];
    {
        int r = w*16 + lr;
        unsigned base = uQ + r*128;
#pragma unroll
        for (int ks = 0; ks < 4; ks++)
            ldsm4(qa[ks], base + (((2*ks + ko) ^ (r & 7)) << 4));
    }

    float oa[8][4];
#pragma unroll
    for (int et = 0; et < 8; et++)
#pragma unroll
        for (int j = 0; j < 4; j++) oa[et][j] = 0.f;
    float m0v = -INFINITY, m1v = -INFINITY, l0v = 0.f, l1v = 0.f;

    for (int n0k = 0; n0k < LL; n0k += 64) {
        __syncthreads();
#pragma unroll
        for (int i = 0; i < 2; i++) {
            int u = tid + i*256;
            int row = u >> 3, g = u & 7;
            size_t gr = (bL + n0k + row) * QKVN + g*8;
            int so = row*128 + ((g ^ (row & 7)) << 4);
            *(uint4*)(sK + so) = *(const uint4*)&kp[gr];
            *(uint4*)(sV + so) = *(const uint4*)&vp[gr];
        }
        __syncthreads();

        float sa[8][4];
#pragma unroll
        for (int nt = 0; nt < 8; nt++)
#pragma unroll
            for (int j = 0; j < 4; j++) sa[nt][j] = 0.f;
#pragma unroll
        for (int ks = 0; ks < 4; ks++) {
#pragma unroll
            for (int nb = 0; nb < 4; nb++) {
                unsigned bfr[4];
                int r = nb*16 + lr;
                ldsm4(bfr, uK + r*128 + (((2*ks + ko) ^ (r & 7)) << 4));
                unsigned b0[2] = {bfr[0], bfr[2]};
                unsigned b1[2] = {bfr[1], bfr[3]};
                mma_bf16(sa[nb*2],     qa[ks], b0);
                mma_bf16(sa[nb*2 + 1], qa[ks], b1);
            }
        }

        float rmax0 = -INFINITY, rmax1 = -INFINITY;
#pragma unroll
        for (int nt = 0; nt < 8; nt++) {
            sa[nt][0] *= 0.125f; sa[nt][1] *= 0.125f;
            sa[nt][2] *= 0.125f; sa[nt][3] *= 0.125f;
            unsigned char mk0 = mask[bL + n0k + nt*8 + off*2];
            unsigned char mk1 = mask[bL + n0k + nt*8 + off*2 + 1];
            if (mk0) { sa[nt][0] = -INFINITY; sa[nt][2] = -INFINITY; }
            if (mk1) { sa[nt][1] = -INFINITY; sa[nt][3] = -INFINITY; }
            rmax0 = fmaxf(rmax0, fmaxf(sa[nt][0], sa[nt][1]));
            rmax1 = fmaxf(rmax1, fmaxf(sa[nt][2], sa[nt][3]));
        }
        rmax0 = fmaxf(rmax0, __shfl_xor_sync(0xffffffffu, rmax0, 1));
        rmax0 = fmaxf(rmax0, __shfl_xor_sync(0xffffffffu, rmax0, 2));
        rmax1 = fmaxf(rmax1, __shfl_xor_sync(0xffffffffu, rmax1, 1));
        rmax1 = fmaxf(rmax1, __shfl_xor_sync(0xffffffffu, rmax1, 2));
        float mn0 = fmaxf(m0v, rmax0), mn1 = fmaxf(m1v, rmax1);
        float c0 = __expf(m0v - mn0), c1 = __expf(m1v - mn1);
        float rs0 = 0.f, rs1 = 0.f;
#pragma unroll
        for (int nt = 0; nt < 8; nt++) {
            float p0 = __expf(sa[nt][0] - mn0);
            float p1 = __expf(sa[nt][1] - mn0);
            float p2 = __expf(sa[nt][2] - mn1);
            float p3 = __expf(sa[nt][3] - mn1);
            rs0 += p0 + p1; rs1 += p2 + p3;
            *(unsigned*)(sP + s*128       + ((nt ^ (s & 7)) << 4) + off*4) = packbf2(p0, p1);
            *(unsigned*)(sP + (s+8)*128   + ((nt ^ (s & 7)) << 4) + off*4) = packbf2(p2, p3);
        }
        rs0 += __shfl_xor_sync(0xffffffffu, rs0, 1);
        rs0 += __shfl_xor_sync(0xffffffffu, rs0, 2);
        rs1 += __shfl_xor_sync(0xffffffffu, rs1, 1);
        rs1 += __shfl_xor_sync(0xffffffffu, rs1, 2);
        l0v = l0v * c0 + rs0; l1v = l1v * c1 + rs1;
        m0v = mn0; m1v = mn1;
#pragma unroll
        for (int et = 0; et < 8; et++) {
            oa[et][0] *= c0; oa[et][1] *= c0;
            oa[et][2] *= c1; oa[et][3] *= c1;
        }
        __syncwarp();

#pragma unroll
        for (int ksp = 0; ksp < 4; ksp++) {
            unsigned pa[4];
            {
                int r = lr;
                ldsm4(pa, uP + r*128 + (((2*ksp + ko) ^ (r & 7)) << 4));
            }
            int key = ksp*16 + lr;
#pragma unroll
            for (int j = 0; j < 4; j++) {
                unsigned vfr[4];
                ldsm4t(vfr, uV + key*128 + (((2*j + ko) ^ (key & 7)) << 4));
                unsigned be0[2] = {vfr[0], vfr[1]};
                unsigned be1[2] = {vfr[2], vfr[3]};
                mma_bf16(oa[j*2],     pa, be0);
                mma_bf16(oa[j*2 + 1], pa, be1);
            }
        }
    }

    float inv0 = 1.f / l0v, inv1 = 1.f / l1v;
#pragma unroll
    for (int et = 0; et < 8; et++) {
        size_t r0 = (bL + qr + w*16 + s    ) * Dd + h*Ee + et*8 + off*2;
        size_t r1 = (bL + qr + w*16 + s + 8) * Dd + h*Ee + et*8 + off*2;
        *(unsigned*)&o[r0] = packbf2(oa[et][0]*inv0, oa[et][1]*inv0);
        *(unsigned*)&o[r1] = packbf2(oa[et][2]*inv1, oa[et][3]*inv1);
    }
}

// ---------------- causal depthwise conv (KC=4) + SiLU ------------------------
__global__ void conv_silu_k(const float* __restrict__ xz,
                            const float* __restrict__ cw,
                            const float* __restrict__ cb,
                            float* __restrict__ uact)
{
    int idx = blockIdx.x * 256 + threadIdx.x;
    int r = idx >> 10;
    int j = idx & 1023;
    int t = r % LL;
    float acc = cb[j];
#pragma unroll
    for (int kk = 0; kk < 4; kk++) {
        int tt = t + kk - 3;
        if (tt >= 0)
            acc = fmaf(xz[(size_t)(r + kk - 3) * (2*DI) + j], cw[j*4 + kk], acc);
    }
    uact[idx] = acc / (1.f + expf(-acc));
}

// ---- selective scan + fused dt_proj/softplus + gate, 3-stage cp.async ------
// Per stage (floats): xrow[16][164] (xdbc cols 0:160, pad 164) | u[16][16] | z[16][16]
#define SCAN_STG 3136   /* 16*164 + 256 + 256 */
__global__ __launch_bounds__(512) void scan_gate_k(
    const float* __restrict__ uact,
    const float* __restrict__ xdbc, const float* __restrict__ A_log,
    const float* __restrict__ xz,   const float* __restrict__ Dssm,
    const float* __restrict__ wdt,  const float* __restrict__ bdt,
    __nv_bfloat16* __restrict__ y)
{
    extern __shared__ __align__(16) float smS[];
    float* swdt = smS + 3*SCAN_STG;   // [16][32]
    float* sdb  = swdt + 512;         // [16]
    float* sdtW = sdb + 16;           // [16][17]
    float* spw  = sdtW + 272;         // [16][16][33]
    const unsigned stgU = (unsigned)__cvta_generic_to_shared(smS);

    int b = blockIdx.y;
    int d0 = blockIdx.x * 16;
    int tid = threadIdx.x;
    int w = tid >> 5, l = tid & 31;
    int d = d0 + w;
    float a0 = -expf(A_log[d*Ss + l]);
    float a1 = -expf(A_log[d*Ss + l + 32]);
    float dD = Dssm[d];
    float h0 = 0.f, h1 = 0.f;
    size_t base = (size_t)b * LL;

    const int rr = l >> 1;
    const int half = l & 1;

    // preload dt weights/bias (covered by first loop __syncthreads)
    swdt[tid] = wdt[(d0 + (tid >> 5))*Rr + (tid & 31)];
    if (tid < 16) sdb[tid] = bdt[d0 + tid];

    // staging maps: 768 16B transfers/tile: xrow 0..639, u 640..703, z 704..767
    const int rowA = tid / 40, segA = tid % 40;
    const float* srcA = xdbc + (base + rowA) * 160 + segA*4;
    const unsigned dstA = stgU + ((rowA*164 + segA*4) << 2);
    const bool hasB = tid < 256;
    const float* srcB = nullptr; unsigned dstB = 0; int incB = 0;
    if (tid < 128) {
        int i2 = 512 + tid, r2 = i2 / 40, s2 = i2 % 40;
        srcB = xdbc + (base + r2) * 160 + s2*4;
        dstB = stgU + ((r2*164 + s2*4) << 2);
        incB = 16*160;
    } else if (tid < 192) {
        int j = tid - 128, r2 = j >> 2, c2 = (j & 3)*4;
        srcB = uact + (base + r2) * DI + d0 + c2;
        dstB = stgU + ((2624 + r2*16 + c2) << 2);
        incB = 16*DI;
    } else if (tid < 256) {
        int j = tid - 192, r2 = j >> 2, c2 = (j & 3)*4;
        srcB = xz + (base + r2) * (size_t)(2*DI) + DI + d0 + c2;
        dstB = stgU + ((2880 + r2*16 + c2) << 2);
        incB = 16*2*DI;
    }
    const int incA = 16*160;
    const int nt = LL / 16;   // 72

    // prologue
    cpa16(dstA, srcA);
    if (hasB) cpa16(dstB, srcB);
    cpa_commit();

    for (int t = 0; t < nt; t++) {
        const int cur = t % 3;
        if (t + 1 < nt) {
            const int nxt = (t + 1) % 3;
            cpa16(dstA + nxt*SCAN_STG*4, srcA + (size_t)(t + 1)*incA);
            if (hasB) cpa16(dstB + nxt*SCAN_STG*4, srcB + (size_t)(t + 1)*incB);
            cpa_commit();
            cpa_wait<1>();
        } else {
            cpa_wait<0>();
        }
        __syncthreads();

        const float* stg = smS + cur*SCAN_STG;
        const float* suS = stg + 2624;
        const float* szS = stg + 2880;
        const int t0 = t * 16;

        // delta = softplus(dt_r @ wdt[d] + b): warp w computes channel d0+w
        {
            int ttd = l >> 1, halfd = l & 1;
            const float* xr = stg + ttd*164 + halfd*16;
            const float* wv = swdt + w*32 + halfd*16;
            float dot = 0.f;
#pragma unroll
            for (int j = 0; j < 16; j++) dot = fmaf(xr[j], wv[j], dot);
            dot += __shfl_xor_sync(0xffffffffu, dot, 1);
            if (halfd == 0) {
                float dv = dot + sdb[w];
                dv = (dv > 20.f) ? dv : log1pf(expf(dv));
                sdtW[w*17 + ttd] = dv;
            }
        }
        __syncwarp();

#pragma unroll 4
        for (int tt = 0; tt < 16; tt++) {
            float dt  = sdtW[w*17 + tt];
            float dtu = dt * suS[tt*16 + w];
            float dA0 = __expf(dt * a0);
            float dA1 = __expf(dt * a1);
            h0 = fmaf(h0, dA0, dtu * stg[tt*164 + 32 + l]);
            h1 = fmaf(h1, dA1, dtu * stg[tt*164 + 64 + l]);
            spw[(w*16 + tt)*33 + l] = fmaf(h1, stg[tt*164 + 128 + l], h0 * stg[tt*164 + 96 + l]);
        }
        __syncwarp();

        float accv = 0.f;
#pragma unroll
        for (int i = 0; i < 16; i++) accv += spw[(w*16 + rr)*33 + half*16 + i];
        accv += __shfl_xor_sync(0xffffffffu, accv, 1);
        if (half == 0) {
            float uu = suS[rr*16 + w];
            float zz = szS[rr*16 + w];
            float yv = fmaf(uu, dD, accv);
            y[(base + t0 + rr) * DI + d] = __float2bfloat16(yv * (zz / (1.f + __expf(-zz))));
        }
    }
}

// ---------------- double LayerNorm on pre-summed residual --------------------
__device__ __forceinline__ float blockSum128(float v, float* sm)
{
#pragma unroll
    for (int offx = 16; offx > 0; offx >>= 1)
        v += __shfl_xor_sync(0xffffffffu, v, offx);
    if ((threadIdx.x & 31) == 0) sm[threadIdx.x >> 5] = v;
    __syncthreads();
    float r = sm[0] + sm[1] + sm[2] + sm[3];
    __syncthreads();
    return r;
}

__global__ __launch_bounds__(128) void ln2_k(
    const float* __restrict__ hsum,
    const float* __restrict__ g1, const float* __restrict__ b1,
    const float* __restrict__ g2, const float* __restrict__ b2,
    float* __restrict__ h, __nv_bfloat16* __restrict__ hn)
{
    __shared__ float sm[4];
    int r = blockIdx.x, tid = threadIdx.x;
    size_t base = (size_t)r * Dd;
    float vv[4];
#pragma unroll
    for (int i = 0; i < 4; i++) vv[i] = hsum[base + tid + i*128];
    float s = vv[0] + vv[1] + vv[2] + vv[3];
    float mean = blockSum128(s, sm) * (1.f/512.f);
    float sq = 0.f;
#pragma unroll
    for (int i = 0; i < 4; i++) { float dd = vv[i] - mean; sq = fmaf(dd, dd, sq); }
    float var = blockSum128(sq, sm) * (1.f/512.f);
    float inv = rsqrtf(var + 1e-5f);
    float hv[4];
#pragma unroll
    for (int i = 0; i < 4; i++) {
        int c = tid + i*128;
        hv[i] = (vv[i] - mean) * inv * g1[c] + b1[c];
        h[base+c] = hv[i];
    }
    float s2 = hv[0] + hv[1] + hv[2] + hv[3];
    float mean2 = blockSum128(s2, sm) * (1.f/512.f);
    float sq2 = 0.f;
#pragma unroll
    for (int i = 0; i < 4; i++) { float dd = hv[i] - mean2; sq2 = fmaf(dd, dd, sq2); }
    float var2 = blockSum128(sq2, sm) * (1.f/512.f);
    float inv2 = rsqrtf(var2 + 1e-6f);
#pragma unroll
    for (int i = 0; i < 4; i++) {
        int c = tid + i*128;
        hn[base+c] = __float2bfloat16((hv[i] - mean2) * inv2 * g2[c] + b2[c]);
    }
}

// ---------------- launch -----------------------------------------------------
extern "C" void kernel_launch(void* const* d_in, const int* in_sizes, int n_in,
                              void* d_out, int out_size)
{
    const float* x            = (const float*)d_in[0];
    const unsigned char* mask = (const unsigned char*)d_in[1];
    const float* Wq = (const float*)d_in[2];   const float* bq = (const float*)d_in[3];
    const float* Wk = (const float*)d_in[4];   const float* bk = (const float*)d_in[5];
    const float* Wv = (const float*)d_in[6];   const float* bv = (const float*)d_in[7];
    const float* Wo = (const float*)d_in[8];   const float* bo = (const float*)d_in[9];
    const float* in_proj_w = (const float*)d_in[10];
    const float* conv_w    = (const float*)d_in[11];
    const float* conv_b    = (const float*)d_in[12];
    const float* x_proj_w  = (const float*)d_in[13];
    const float* dt_proj_w = (const float*)d_in[14];
    const float* dt_proj_b = (const float*)d_in[15];
    const float* A_log     = (const float*)d_in[16];
    const float* D_ssm     = (const float*)d_in[17];
    const float* out_proj_w= (const float*)d_in[18];
    const float* ln1_g = (const float*)d_in[19]; const float* ln1_b = (const float*)d_in[20];
    const float* ffn_w1= (const float*)d_in[21]; const float* ffn_b1= (const float*)d_in[22];
    const float* ffn_w2= (const float*)d_in[23]; const float* ffn_b2= (const float*)d_in[24];
    const float* ln2_g = (const float*)d_in[25]; const float* ln2_b = (const float*)d_in[26];
    float* out = (float*)d_out;

    __nv_bfloat16 *xbf,*wqkvb,*wob,*winb,*woutb,*wf1b,*wf2b;
    float *bqkv;
    __nv_bfloat16 *qkv, *attnO, *y, *hn, *mid;
    float *attn_out,*xz,*uact,*xdbc,*hsum,*h;
    cudaGetSymbolAddress((void**)&xbf,   g_xbf);
    cudaGetSymbolAddress((void**)&wqkvb, g_wqkv);
    cudaGetSymbolAddress((void**)&bqkv,  g_bqkv);
    cudaGetSymbolAddress((void**)&wob,   g_wo);
    cudaGetSymbolAddress((void**)&winb,  g_win);
    cudaGetSymbolAddress((void**)&woutb, g_wout);
    cudaGetSymbolAddress((void**)&wf1b,  g_wf1);
    cudaGetSymbolAddress((void**)&wf2b,  g_wf2);
    cudaGetSymbolAddress((void**)&qkv,      g_qkv);
    cudaGetSymbolAddress((void**)&attnO,    g_attnO);
    cudaGetSymbolAddress((void**)&attn_out, g_attn_out);
    cudaGetSymbolAddress((void**)&xz,       g_xz);
    cudaGetSymbolAddress((void**)&uact,     g_uact);
    cudaGetSymbolAddress((void**)&xdbc,     g_xdbc);
    cudaGetSymbolAddress((void**)&y,        g_y);
    cudaGetSymbolAddress((void**)&hsum,     g_hsum);
    cudaGetSymbolAddress((void**)&h,        g_h);
    cudaGetSymbolAddress((void**)&hn,       g_hn);
    cudaGetSymbolAddress((void**)&mid,      g_mid);

    static cudaStream_t s_attn = nullptr;
    static cudaEvent_t  e_fork = nullptr, e_join = nullptr;
    if (s_attn == nullptr) {
        cudaStreamCreateWithFlags(&s_attn, cudaStreamNonBlocking);
        cudaEventCreateWithFlags(&e_fork, cudaEventDisableTiming);
        cudaEventCreateWithFlags(&e_join, cudaEventDisableTiming);
    }

    const int MY = Mrows / 128;   // 72
    const int attn_smem = 32768 + 8*2048;                       // 49152 bytes
    const int scan_smem = (3*SCAN_STG + 512 + 16 + 272 + 16*16*33) * 4;   // 74624 bytes
    cudaFuncSetAttribute(attn_bf, cudaFuncAttributeMaxDynamicSharedMemorySize, attn_smem);
    cudaFuncSetAttribute(scan_gate_k, cudaFuncAttributeMaxDynamicSharedMemorySize, scan_smem);

    #define CVT(src, dst, n) cvt_bf_k<<<((n)/4 + 255)/256, 256, 0, 0>>>(src, dst, n)
    #define CVT_S(src, dst, n) cvt_bf_k<<<((n)/4 + 255)/256, 256, 0, s_attn>>>(src, dst, n)

    // ---- x -> bf16 (needed by both branches), then fork ----
    CVT(x, xbf, Mrows*Dd);
    cudaEventRecord(e_fork, 0);
    cudaStreamWaitEvent(s_attn, e_fork, 0);

    // attention branch (s_attn)
    CVT_S(Wq, wqkvb,            Dd*Dd);
    CVT_S(Wk, wqkvb + Dd*Dd,    Dd*Dd);
    CVT_S(Wv, wqkvb + 2*Dd*Dd,  Dd*Dd);
    CVT_S(Wo, wob, Dd*Dd);
    concat_bias_k<<<(QKVN + 255)/256, 256, 0, s_attn>>>(bq, bk, bv, bqkv);
    gemm_bb<EPI_NONE,1><<<dim3(QKVN/64, MY), 256, 0, s_attn>>>(xbf, Dd, wqkvb, bqkv, nullptr, nullptr, qkv, Mrows, QKVN, Dd);
    attn_bf<<<dim3(LL/128, Hh, Bsz), 256, attn_smem, s_attn>>>(qkv, mask, attnO);
    gemm_bb<EPI_NONE,0><<<dim3(Dd/64,   MY), 256, 0, s_attn>>>(attnO, Dd, wob, bo, nullptr, nullptr, attn_out, Mrows, Dd, Dd);
    cudaEventRecord(e_join, s_attn);

    // mamba branch (stream 0)
    CVT(in_proj_w, winb, 2*DI*Dd);
    CVT(out_proj_w, woutb, Dd*DI);
    CVT(ffn_w1, wf1b, DFF*Dd);
    CVT(ffn_w2, wf2b, Dd*DFF);
    gemm_bb<EPI_NONE,0><<<dim3(2*DI/64, MY), 256>>>(xbf, Dd, winb, nullptr, nullptr, nullptr, xz, Mrows, 2*DI, Dd);
    conv_silu_k<<<Mrows*DI/256, 256>>>(xz, conv_w, conv_b, uact);
    gemm_tf32<EPI_NONE><<<dim3(3,       MY), 256>>>(uact, DI, x_proj_w, nullptr, xdbc, Mrows, 160, DI);
    scan_gate_k<<<dim3(DI/16, Bsz), 512, scan_smem>>>(uact, xdbc, A_log, xz, D_ssm,
                                                      dt_proj_w, dt_proj_b, y);

    // ---- join, then out_proj with fused residual adds ----
    cudaStreamWaitEvent(0, e_join, 0);
    gemm_bb<EPI_ADD2,0><<<dim3(Dd/64,   MY), 256>>>(y, DI, woutb, nullptr, x, attn_out, hsum, Mrows, Dd, DI);

    // double layernorm
    ln2_k<<<Mrows, 128>>>(hsum, ln1_g, ln1_b, ln2_g, ln2_b, h, hn);

    // FFN
    gemm_bb<EPI_GELU,1><<<dim3(DFF/64, MY), 256>>>(hn, Dd, wf1b, ffn_b1, nullptr, nullptr, mid, Mrows, DFF, Dd);
    gemm_bb<EPI_ADD,0><<<dim3(Dd/64,   MY), 256>>>(mid, DFF, wf2b, ffn_b2, h, nullptr, out, Mrows, Dd, DFF);

    #undef CVT
    #undef CVT_S
}